// round 3
// baseline (speedup 1.0000x reference)
#include <cuda_runtime.h>

// Problem constants
#define BB  8
#define SS  1024
#define DD  1024
#define HH  16
#define DKK 64

// Scratch (allocation-free rule: __device__ globals)
__device__ float g_q[BB * HH * SS * DKK];
__device__ float g_k[BB * HH * SS * DKK];
__device__ float g_v[BB * HH * SS * DKK];
__device__ float g_ctx[BB * SS * DD];

// Tiling
#define BM 64
#define BN 64
#define BK 16
#define AST 68  // padded stride for transposed-stored tiles

// ---------------------------------------------------------------------------
// proj: out[b,h,s,d] = sum_k X[b*S+s,k] * W[h*DK+d,k] + bias[h*DK+d]
// GEMM C = X[M,K] @ W[N,K]^T, M=8192, N=1024, K=1024, BHSD output layout
// ---------------------------------------------------------------------------
__global__ __launch_bounds__(256) void proj_kernel(const float* __restrict__ X,
                                                   const float* __restrict__ W,
                                                   const float* __restrict__ bias,
                                                   float* __restrict__ out) {
    __shared__ float As[BK][AST];
    __shared__ float Bs[BK][AST];
    const int tid = threadIdx.x;
    const int tx = tid & 15, ty = tid >> 4;
    const int m0 = blockIdx.y * BM, n0 = blockIdx.x * BN;
    const int lr = tid >> 2, lc = (tid & 3) << 2;

    float acc[4][4] = {};

    for (int kt = 0; kt < DD; kt += BK) {
        float4 a = *(const float4*)&X[(size_t)(m0 + lr) * DD + kt + lc];
        float4 b = *(const float4*)&W[(size_t)(n0 + lr) * DD + kt + lc];
        __syncthreads();
        As[lc + 0][lr] = a.x; As[lc + 1][lr] = a.y;
        As[lc + 2][lr] = a.z; As[lc + 3][lr] = a.w;
        Bs[lc + 0][lr] = b.x; Bs[lc + 1][lr] = b.y;
        Bs[lc + 2][lr] = b.z; Bs[lc + 3][lr] = b.w;
        __syncthreads();
#pragma unroll
        for (int kk = 0; kk < BK; ++kk) {
            float4 av = *(const float4*)&As[kk][ty * 4];
            float4 bv = *(const float4*)&Bs[kk][tx * 4];
            float aa[4] = {av.x, av.y, av.z, av.w};
            float bb[4] = {bv.x, bv.y, bv.z, bv.w};
#pragma unroll
            for (int i = 0; i < 4; ++i)
#pragma unroll
                for (int j = 0; j < 4; ++j) acc[i][j] += aa[i] * bb[j];
        }
    }

#pragma unroll
    for (int i = 0; i < 4; ++i) {
        const int m = m0 + ty * 4 + i;
        const int bI = m >> 10, s = m & 1023;
#pragma unroll
        for (int j = 0; j < 4; ++j) {
            const int n = n0 + tx * 4 + j;
            const int h = n >> 6, d = n & 63;
            out[((size_t)(bI * HH + h) * SS + s) * DKK + d] = acc[i][j] + bias[n];
        }
    }
}

// ---------------------------------------------------------------------------
// out-proj: out[m,n] = sum_k ctx[m,k]*Wo[n,k] + bo[n] + Qres[m,n]
// ---------------------------------------------------------------------------
__global__ __launch_bounds__(256) void outproj_kernel(const float* __restrict__ Xc,
                                                      const float* __restrict__ W,
                                                      const float* __restrict__ bias,
                                                      const float* __restrict__ Qres,
                                                      float* __restrict__ out) {
    __shared__ float As[BK][AST];
    __shared__ float Bs[BK][AST];
    const int tid = threadIdx.x;
    const int tx = tid & 15, ty = tid >> 4;
    const int m0 = blockIdx.y * BM, n0 = blockIdx.x * BN;
    const int lr = tid >> 2, lc = (tid & 3) << 2;

    float acc[4][4] = {};

    for (int kt = 0; kt < DD; kt += BK) {
        float4 a = *(const float4*)&Xc[(size_t)(m0 + lr) * DD + kt + lc];
        float4 b = *(const float4*)&W[(size_t)(n0 + lr) * DD + kt + lc];
        __syncthreads();
        As[lc + 0][lr] = a.x; As[lc + 1][lr] = a.y;
        As[lc + 2][lr] = a.z; As[lc + 3][lr] = a.w;
        Bs[lc + 0][lr] = b.x; Bs[lc + 1][lr] = b.y;
        Bs[lc + 2][lr] = b.z; Bs[lc + 3][lr] = b.w;
        __syncthreads();
#pragma unroll
        for (int kk = 0; kk < BK; ++kk) {
            float4 av = *(const float4*)&As[kk][ty * 4];
            float4 bv = *(const float4*)&Bs[kk][tx * 4];
            float aa[4] = {av.x, av.y, av.z, av.w};
            float bb[4] = {bv.x, bv.y, bv.z, bv.w};
#pragma unroll
            for (int i = 0; i < 4; ++i)
#pragma unroll
                for (int j = 0; j < 4; ++j) acc[i][j] += aa[i] * bb[j];
        }
    }

#pragma unroll
    for (int i = 0; i < 4; ++i) {
        const size_t m = m0 + ty * 4 + i;
#pragma unroll
        for (int j = 0; j < 4; ++j) {
            const int n = n0 + tx * 4 + j;
            out[m * DD + n] = acc[i][j] + bias[n] + Qres[m * DD + n];
        }
    }
}

// ---------------------------------------------------------------------------
// scores[bh,m,n] = (q[bh,m,:] . k[bh,n,:]) / 8, mask -> -1e9
// Per (b,h): GEMM M=N=1024, K=64 (A@B^T)
// ---------------------------------------------------------------------------
__global__ __launch_bounds__(256) void scores_kernel(const float* __restrict__ q,
                                                     const float* __restrict__ k,
                                                     const unsigned char* __restrict__ mask,
                                                     float* __restrict__ scores) {
    const int bh = blockIdx.z;
    const int bI = bh >> 4;  // /H
    const float* A = q + (size_t)bh * SS * DKK;
    const float* Bp = k + (size_t)bh * SS * DKK;

    __shared__ float As[BK][AST];
    __shared__ float Bs[BK][AST];
    const int tid = threadIdx.x;
    const int tx = tid & 15, ty = tid >> 4;
    const int m0 = blockIdx.y * BM, n0 = blockIdx.x * BN;
    const int lr = tid >> 2, lc = (tid & 3) << 2;

    float acc[4][4] = {};

    for (int kt = 0; kt < DKK; kt += BK) {
        float4 a = *(const float4*)&A[(size_t)(m0 + lr) * DKK + kt + lc];
        float4 b = *(const float4*)&Bp[(size_t)(n0 + lr) * DKK + kt + lc];
        __syncthreads();
        As[lc + 0][lr] = a.x; As[lc + 1][lr] = a.y;
        As[lc + 2][lr] = a.z; As[lc + 3][lr] = a.w;
        Bs[lc + 0][lr] = b.x; Bs[lc + 1][lr] = b.y;
        Bs[lc + 2][lr] = b.z; Bs[lc + 3][lr] = b.w;
        __syncthreads();
#pragma unroll
        for (int kk = 0; kk < BK; ++kk) {
            float4 av = *(const float4*)&As[kk][ty * 4];
            float4 bv = *(const float4*)&Bs[kk][tx * 4];
            float aa[4] = {av.x, av.y, av.z, av.w};
            float bb[4] = {bv.x, bv.y, bv.z, bv.w};
#pragma unroll
            for (int i = 0; i < 4; ++i)
#pragma unroll
                for (int j = 0; j < 4; ++j) acc[i][j] += aa[i] * bb[j];
        }
    }

    float* srow = scores + (size_t)bh * SS * SS;
    const unsigned char* mrow = mask + (size_t)bI * SS * SS;
#pragma unroll
    for (int i = 0; i < 4; ++i) {
        const int m = m0 + ty * 4 + i;
#pragma unroll
        for (int j = 0; j < 4; ++j) {
            const int n = n0 + tx * 4 + j;
            float v = acc[i][j] * 0.125f;
            if (mrow[(size_t)m * SS + n]) v = -1e9f;
            srow[(size_t)m * SS + n] = v;
        }
    }
}

// ---------------------------------------------------------------------------
// softmax over last dim (row length 1024), one block per row
// ---------------------------------------------------------------------------
__global__ __launch_bounds__(256) void softmax_kernel(const float* __restrict__ scores,
                                                      float* __restrict__ attn) {
    const size_t row = blockIdx.x;
    const float4* src = (const float4*)(scores + row * SS);
    const int t = threadIdx.x;
    float4 x = src[t];

    float m = fmaxf(fmaxf(x.x, x.y), fmaxf(x.z, x.w));
#pragma unroll
    for (int o = 16; o; o >>= 1) m = fmaxf(m, __shfl_xor_sync(0xffffffffu, m, o));

    __shared__ float smax[8];
    __shared__ float ssum[8];
    const int wid = t >> 5, lane = t & 31;
    if (lane == 0) smax[wid] = m;
    __syncthreads();
    float mx = smax[0];
#pragma unroll
    for (int i = 1; i < 8; ++i) mx = fmaxf(mx, smax[i]);

    float4 e;
    e.x = expf(x.x - mx); e.y = expf(x.y - mx);
    e.z = expf(x.z - mx); e.w = expf(x.w - mx);
    float s = e.x + e.y + e.z + e.w;
#pragma unroll
    for (int o = 16; o; o >>= 1) s += __shfl_xor_sync(0xffffffffu, s, o);
    if (lane == 0) ssum[wid] = s;
    __syncthreads();
    float tot = 0.f;
#pragma unroll
    for (int i = 0; i < 8; ++i) tot += ssum[i];

    const float inv = 1.0f / tot;
    float4 r = make_float4(e.x * inv, e.y * inv, e.z * inv, e.w * inv);
    ((float4*)(attn + row * SS))[t] = r;
}

// ---------------------------------------------------------------------------
// ctx[b,m,h,d] = sum_n attn[bh,m,n] * v[bh,n,d]   (A@B, K=1024, N=64)
// ---------------------------------------------------------------------------
__global__ __launch_bounds__(256) void context_kernel(const float* __restrict__ attn,
                                                      const float* __restrict__ v,
                                                      float* __restrict__ ctx) {
    const int bh = blockIdx.z;
    const int h = bh & 15, bI = bh >> 4;
    const float* A = attn + (size_t)bh * SS * SS;
    const float* Bp = v + (size_t)bh * SS * DKK;

    __shared__ float As[BK][AST];
    __shared__ float Bs[BK][BN];
    const int tid = threadIdx.x;
    const int tx = tid & 15, ty = tid >> 4;
    const int m0 = blockIdx.y * BM;
    const int lr = tid >> 2, lc = (tid & 3) << 2;
    const int kr = tid >> 4, kc = (tid & 15) << 2;

    float acc[4][4] = {};

    for (int kt = 0; kt < SS; kt += BK) {
        float4 a = *(const float4*)&A[(size_t)(m0 + lr) * SS + kt + lc];
        float4 b = *(const float4*)&Bp[(size_t)(kt + kr) * DKK + kc];
        __syncthreads();
        As[lc + 0][lr] = a.x; As[lc + 1][lr] = a.y;
        As[lc + 2][lr] = a.z; As[lc + 3][lr] = a.w;
        *(float4*)&Bs[kr][kc] = b;
        __syncthreads();
#pragma unroll
        for (int kk = 0; kk < BK; ++kk) {
            float4 av = *(const float4*)&As[kk][ty * 4];
            float4 bv = *(const float4*)&Bs[kk][tx * 4];
            float aa[4] = {av.x, av.y, av.z, av.w};
            float bb[4] = {bv.x, bv.y, bv.z, bv.w};
#pragma unroll
            for (int i = 0; i < 4; ++i)
#pragma unroll
                for (int j = 0; j < 4; ++j) acc[i][j] += aa[i] * bb[j];
        }
    }

#pragma unroll
    for (int i = 0; i < 4; ++i) {
        const int m = m0 + ty * 4 + i;
#pragma unroll
        for (int j = 0; j < 4; ++j) {
            const int d = tx * 4 + j;
            ctx[(((size_t)bI * SS + m) * HH + h) * DKK + d] = acc[i][j];
        }
    }
}

// ---------------------------------------------------------------------------
// launch
// ---------------------------------------------------------------------------
extern "C" void kernel_launch(void* const* d_in, const int* in_sizes, int n_in,
                              void* d_out, int out_size) {
    const float* Q  = (const float*)d_in[0];
    const float* K  = (const float*)d_in[1];
    const float* V  = (const float*)d_in[2];
    const unsigned char* mask = (const unsigned char*)d_in[3];
    const float* Wq = (const float*)d_in[4];
    const float* bq = (const float*)d_in[5];
    const float* Wk = (const float*)d_in[6];
    const float* bk = (const float*)d_in[7];
    const float* Wv = (const float*)d_in[8];
    const float* bv = (const float*)d_in[9];
    const float* Wo = (const float*)d_in[10];
    const float* bo = (const float*)d_in[11];

    float* out    = (float*)d_out;                      // [B,S,D]   8,388,608
    float* attn   = out + (size_t)BB * SS * DD;         // [B,H,S,S] 134,217,728
    float* scores = attn + (size_t)BB * HH * SS * SS;   // [B,H,S,S] 134,217,728

    float *gq, *gk, *gv, *gctx;
    cudaGetSymbolAddress((void**)&gq, g_q);
    cudaGetSymbolAddress((void**)&gk, g_k);
    cudaGetSymbolAddress((void**)&gv, g_v);
    cudaGetSymbolAddress((void**)&gctx, g_ctx);

    const dim3 projGrid(DD / BN, (BB * SS) / BM);       // (16,128)
    proj_kernel<<<projGrid, 256>>>(Q, Wq, bq, gq);
    proj_kernel<<<projGrid, 256>>>(K, Wk, bk, gk);
    proj_kernel<<<projGrid, 256>>>(V, Wv, bv, gv);

    const dim3 scoreGrid(SS / BN, SS / BM, BB * HH);    // (16,16,128)
    scores_kernel<<<scoreGrid, 256>>>(gq, gk, mask, scores);

    softmax_kernel<<<BB * HH * SS, 256>>>(scores, attn);

    const dim3 ctxGrid(1, SS / BM, BB * HH);            // (1,16,128)
    context_kernel<<<ctxGrid, 256>>>(attn, gv, gctx);

    outproj_kernel<<<projGrid, 256>>>(gctx, Wo, bo, Q, out);
}